// round 17
// baseline (speedup 1.0000x reference)
#include <cuda_runtime.h>
#include <cuda_bf16.h>
#include <cstdint>
#include <cstddef>

#define Bn 8
#define Tn 2048
#define Dn 128
#define NPAIR 136              // it <= jt pairs of 16 tiles
#define NPART (Bn * NPAIR)     // 1088 CTAs / partials

// ---- scratch (static device globals; no allocations) ----
__device__ __nv_bfloat16 g_zbf[Bn * Tn * Dn];   // 4 MB
__device__ float        g_z2[Bn * Tn];          // 64 KB
__device__ double       g_part[NPART];          // per-CTA partials
__device__ int          g_ticket;               // zero-init; last CTA resets

__device__ __forceinline__ uint32_t smem_u32(const void* p) {
    uint32_t a;
    asm("{ .reg .u64 t; cvta.to.shared.u64 t, %1; cvt.u32.u64 %0, t; }"
        : "=r"(a) : "l"(p));
    return a;
}

#define LDSM_X4(r0, r1, r2, r3, a) \
    asm volatile("ldmatrix.sync.aligned.m8n8.x4.shared.b16 {%0,%1,%2,%3}, [%4];" \
                 : "=r"(r0), "=r"(r1), "=r"(r2), "=r"(r3) : "r"(a))

// ---- cp.async helpers ----
__device__ __forceinline__ void cp16(uint32_t dst, const void* src) {
    asm volatile("cp.async.cg.shared.global [%0], [%1], 16;" :: "r"(dst), "l"(src));
}
__device__ __forceinline__ void cp8(uint32_t dst, const void* src) {
    asm volatile("cp.async.ca.shared.global [%0], [%1], 8;" :: "r"(dst), "l"(src));
}
#define CP_COMMIT() asm volatile("cp.async.commit_group;" ::: "memory")
#define CP_WAIT1()  asm volatile("cp.async.wait_group 1;"  ::: "memory")
#define CP_WAIT0()  asm volatile("cp.async.wait_group 0;"  ::: "memory")

// ============================================================
// Kernel 1: bf16 cast of z + per-row squared norms (4 rows/warp)
// ============================================================
__global__ void __launch_bounds__(256) prep_kernel(const float* __restrict__ z) {
    const int warp = threadIdx.x >> 5, lane = threadIdx.x & 31;
    const int row0 = blockIdx.x * 32 + warp * 4;
    float4 v[4];
    #pragma unroll
    for (int r = 0; r < 4; r++)
        v[r] = ((const float4*)(z + (size_t)(row0 + r) * Dn))[lane];

    #pragma unroll
    for (int r = 0; r < 4; r++) {
        __nv_bfloat162 p0 = __floats2bfloat162_rn(v[r].x, v[r].y);
        __nv_bfloat162 p1 = __floats2bfloat162_rn(v[r].z, v[r].w);
        uint2 o;
        o.x = *reinterpret_cast<uint32_t*>(&p0);
        o.y = *reinterpret_cast<uint32_t*>(&p1);
        ((uint2*)g_zbf)[(size_t)(row0 + r) * 32 + lane] = o;
    }

    float s[4];
    #pragma unroll
    for (int r = 0; r < 4; r++)
        s[r] = v[r].x * v[r].x + v[r].y * v[r].y + v[r].z * v[r].z + v[r].w * v[r].w;
    #pragma unroll
    for (int off = 16; off; off >>= 1) {
        #pragma unroll
        for (int r = 0; r < 4; r++)
            s[r] += __shfl_xor_sync(0xffffffffu, s[r], off);
    }
    if (lane == 0) {
        #pragma unroll
        for (int r = 0; r < 4; r++) g_z2[row0 + r] = s[r];
    }
}

// ============================================================
// Kernel 2: symmetric-pair Gram + cp.async-pipelined epilogue
// grid = (136, 8) = (pair, b); 256 threads (8 warps, 4x2)
// Stage layout (in dead zi/zj smem after MMA):
//   addr = buf*32768 + warp*4096 + slot*512 + lane*16,  slot 0..7
// ============================================================
#define SM_WSTRIDE 68
#define SMEM_BYTES (2 * 128 * SM_WSTRIDE * 4 + 2 * 128 * 4)

extern __shared__ unsigned char smem_raw[];

// ---- group issue: pass 1 (rows=i, cols=j), 8 x cp16 ----
__device__ __forceinline__ void issueP1(uint32_t slotbase, const float4* gt4,
                                        size_t base0, size_t base1,
                                        int colBase, int q, int HALF) {
    #pragma unroll
    for (int c = 0; c < 4; c++) {
        const int jj = colBase + (HALF * 4 + c) * 8 + 2 * q;
        cp16(slotbase + (2 * c) * 512,     gt4 + ((base0 + jj) >> 1));
        cp16(slotbase + (2 * c + 1) * 512, gt4 + ((base1 + jj) >> 1));
    }
}
// ---- group issue: pass 2 (rows=j, cols=i), 16 x cp8 ----
__device__ __forceinline__ void issueP2(uint32_t slotbase, const float2* gt2,
                                        size_t base2, int colBase, int q, int HALF) {
    #pragma unroll
    for (int c = 0; c < 4; c++) {
        const int jj = colBase + (HALF * 4 + c) * 8 + 2 * q;
        const size_t e0 = base2 + (size_t)jj * Tn;
        cp8(slotbase + (2 * c) * 512,          gt2 + e0);
        cp8(slotbase + (2 * c) * 512 + 8,      gt2 + e0 + 8);
        cp8(slotbase + (2 * c + 1) * 512,      gt2 + e0 + Tn);
        cp8(slotbase + (2 * c + 1) * 512 + 8,  gt2 + e0 + Tn + 8);
    }
}

template<int FM, int HALF>
__device__ __forceinline__ float computeP1(const char* slotptr,
                                           const float (&acc)[2][8][4],
                                           float z2a, float z2b,
                                           const float* z2j,
                                           int colBase, int q, float c0, float c1) {
    float s = 0.f;
    #pragma unroll
    for (int c = 0; c < 4; c++) {
        const int fn = HALF * 4 + c;
        const int jj = colBase + fn * 8 + 2 * q;
        const float zj0 = z2j[jj], zj1 = z2j[jj + 1];
        const float4 gA = *(const float4*)(slotptr + (2 * c) * 512);
        const float4 gB = *(const float4*)(slotptr + (2 * c + 1) * 512);
        const float w00 = __expf(-(gA.x * gA.x * c0 + gA.y * gA.y * c1));
        const float w01 = __expf(-(gA.z * gA.z * c0 + gA.w * gA.w * c1));
        const float w10 = __expf(-(gB.x * gB.x * c0 + gB.y * gB.y * c1));
        const float w11 = __expf(-(gB.z * gB.z * c0 + gB.w * gB.w * c1));
        s += w00 * (z2a + zj0 - 2.f * acc[FM][fn][0]);
        s += w01 * (z2a + zj1 - 2.f * acc[FM][fn][1]);
        s += w10 * (z2b + zj0 - 2.f * acc[FM][fn][2]);
        s += w11 * (z2b + zj1 - 2.f * acc[FM][fn][3]);
    }
    return s;
}

template<int FM, int HALF>
__device__ __forceinline__ float computeP2(const char* slotptr,
                                           const float (&acc)[2][8][4],
                                           float z2a, float z2b,
                                           const float* z2j,
                                           int colBase, int q, float c0, float c1) {
    float s = 0.f;
    #pragma unroll
    for (int c = 0; c < 4; c++) {
        const int fn = HALF * 4 + c;
        const int jj = colBase + fn * 8 + 2 * q;
        const float zj0 = z2j[jj], zj1 = z2j[jj + 1];
        const float4 sA = *(const float4*)(slotptr + (2 * c) * 512);      // e0 | e0+8
        const float4 sB = *(const float4*)(slotptr + (2 * c + 1) * 512);  // e0+Tn | +8
        const float w00 = __expf(-(sA.x * sA.x * c0 + sA.y * sA.y * c1)); // (jj,   ri)
        const float w10 = __expf(-(sA.z * sA.z * c0 + sA.w * sA.w * c1)); // (jj,   ri+8)
        const float w01 = __expf(-(sB.x * sB.x * c0 + sB.y * sB.y * c1)); // (jj+1, ri)
        const float w11 = __expf(-(sB.z * sB.z * c0 + sB.w * sB.w * c1)); // (jj+1, ri+8)
        s += w00 * (zj0 + z2a - 2.f * acc[FM][fn][0]);
        s += w01 * (zj1 + z2a - 2.f * acc[FM][fn][1]);
        s += w10 * (zj0 + z2b - 2.f * acc[FM][fn][2]);
        s += w11 * (zj1 + z2b - 2.f * acc[FM][fn][3]);
    }
    return s;
}

__global__ void __launch_bounds__(256, 2)
main_kernel(const float* __restrict__ gt, const float* __restrict__ sigma,
            float* __restrict__ out) {
    uint32_t* zi  = (uint32_t*)smem_raw;
    uint32_t* zj  = zi + 128 * SM_WSTRIDE;
    float*    z2i = (float*)(zj + 128 * SM_WSTRIDE);
    float*    z2j = z2i + 128;

    // decode (it, jt) with it <= jt from pair index
    int p = blockIdx.x, it = 0;
    while (p >= 16 - it) { p -= 16 - it; it++; }
    const int jt = it + p;
    const int b = blockIdx.y;
    const int i0 = it * 128, j0 = jt * 128;
    const int offDiag = (it != jt);
    const int tid = threadIdx.x;
    const int warp = tid >> 5, lane = tid & 31;

    // ---- L2 prefetch of this CTA's gt tile(s) ----
    {
        const char* gbase = (const char*)gt;
        #pragma unroll
        for (int pp = 0; pp < 4; pp++) {
            int idx = tid + pp * 256;                // 0..1023
            int r = idx >> 3, c = idx & 7;
            const char* a1 = gbase +
                ((size_t)(b * Tn + i0 + r) * Tn + j0) * 8 + (size_t)c * 128;
            asm volatile("prefetch.global.L2 [%0];" :: "l"(a1));
            if (offDiag) {
                const char* a2 = gbase +
                    ((size_t)(b * Tn + j0 + r) * Tn + i0) * 8 + (size_t)c * 128;
                asm volatile("prefetch.global.L2 [%0];" :: "l"(a2));
            }
        }
    }

    // ---- load z tiles (bf16, 16B vectors) ----
    const uint4* zsrc = (const uint4*)g_zbf;     // one row = 16 uint4
    #pragma unroll
    for (int pp = 0; pp < 8; pp++) {
        int idx = tid + pp * 256;                // 0..2047
        int r = idx >> 4, c = idx & 15;
        uint4 vi = zsrc[(size_t)(b * Tn + i0 + r) * 16 + c];
        *((uint4*)(zi + r * SM_WSTRIDE + c * 4)) = vi;
        uint4 vj = zsrc[(size_t)(b * Tn + j0 + r) * 16 + c];
        *((uint4*)(zj + r * SM_WSTRIDE + c * 4)) = vj;
    }
    if (tid < 128) z2i[tid] = g_z2[b * Tn + i0 + tid];
    else           z2j[tid - 128] = g_z2[b * Tn + j0 + (tid - 128)];
    __syncthreads();

    // ---- Gram 128x128 via mma.sync m16n8k16 bf16, ldmatrix operands ----
    const int wm = warp & 3, wn = warp >> 2;     // 4 x 2 warp grid
    const int rowBase = wm * 32, colBase = wn * 64;
    const int gr = lane >> 2, q = lane & 3;

    const uint32_t ziB = smem_u32(zi), zjB = smem_u32(zj);
    const int la = lane & 15, ha = lane >> 4;
    uint32_t aAddr0 = ziB + (uint32_t)((rowBase + la) * SM_WSTRIDE + ha * 4) * 4;
    uint32_t aAddr1 = aAddr0 + 16 * SM_WSTRIDE * 4;
    const int gq = lane >> 3;
    uint32_t bAddr = zjB + (uint32_t)((colBase + (gq >> 1) * 8 + (lane & 7)) * SM_WSTRIDE
                                      + (gq & 1) * 4) * 4;
    const uint32_t FN_STRIDE = 16 * SM_WSTRIDE * 4;

    float acc[2][8][4];
    #pragma unroll
    for (int fm = 0; fm < 2; fm++)
        #pragma unroll
        for (int fn = 0; fn < 8; fn++)
            #pragma unroll
            for (int v = 0; v < 4; v++) acc[fm][fn][v] = 0.f;

    #pragma unroll
    for (int ks = 0; ks < 8; ks++) {
        const uint32_t ko = ks * 32;
        uint32_t a[2][4], bb[4][4];
        LDSM_X4(a[0][0], a[0][1], a[0][2], a[0][3], aAddr0 + ko);
        LDSM_X4(a[1][0], a[1][1], a[1][2], a[1][3], aAddr1 + ko);
        #pragma unroll
        for (int pp = 0; pp < 4; pp++)
            LDSM_X4(bb[pp][0], bb[pp][1], bb[pp][2], bb[pp][3], bAddr + pp * FN_STRIDE + ko);

        #pragma unroll
        for (int pp = 0; pp < 4; pp++) {
            #pragma unroll
            for (int s = 0; s < 2; s++) {
                const int fn = 2 * pp + s;
                const uint32_t b0 = bb[pp][2 * s], b1 = bb[pp][2 * s + 1];
                #pragma unroll
                for (int fm = 0; fm < 2; fm++) {
                    asm volatile(
                        "mma.sync.aligned.m16n8k16.row.col.f32.bf16.bf16.f32 "
                        "{%0,%1,%2,%3}, {%4,%5,%6,%7}, {%8,%9}, {%0,%1,%2,%3};"
                        : "+f"(acc[fm][fn][0]), "+f"(acc[fm][fn][1]),
                          "+f"(acc[fm][fn][2]), "+f"(acc[fm][fn][3])
                        : "r"(a[fm][0]), "r"(a[fm][1]), "r"(a[fm][2]), "r"(a[fm][3]),
                          "r"(b0), "r"(b1));
                }
            }
        }
    }
    __syncthreads();   // all LDSM done; zi/zj become the cp.async stage

    // ---- epilogue: cp.async depth-2 pipeline over groups ----
    const float sg0 = sigma[0], sg1 = sigma[1];
    const float c0 = 1.0f / (2.0f * sg0 * sg0), c1 = 1.0f / (2.0f * sg1 * sg1);
    const float4* gt4 = (const float4*)gt;
    const float2* gt2 = (const float2*)gt;

    const int ri0 = rowBase + gr, ri1 = rowBase + 16 + gr;
    const float z2a0 = z2i[ri0], z2b0 = z2i[ri0 + 8];
    const float z2a1 = z2i[ri1], z2b1 = z2i[ri1 + 8];
    const size_t p1b0f0 = (size_t)(b * Tn + i0 + ri0) * Tn + j0;
    const size_t p1b1f0 = p1b0f0 + (size_t)8 * Tn;
    const size_t p1b0f1 = (size_t)(b * Tn + i0 + ri1) * Tn + j0;
    const size_t p1b1f1 = p1b0f1 + (size_t)8 * Tn;
    const size_t p2f0 = (size_t)(b * Tn + j0) * Tn + i0 + ri0;
    const size_t p2f1 = (size_t)(b * Tn + j0) * Tn + i0 + ri1;

    const uint32_t stA = smem_u32(smem_raw) + (uint32_t)(warp * 4096 + lane * 16);
    const char*    stP = (const char*)smem_raw + warp * 4096 + lane * 16;
    #define BUF_A(bu) (stA + (bu) * 32768)
    #define BUF_P(bu) (stP + (bu) * 32768)

    float sum = 0.f;
    if (offDiag) {
        issueP1(BUF_A(0), gt4, p1b0f0, p1b1f0, colBase, q, 0); CP_COMMIT();
        issueP1(BUF_A(1), gt4, p1b0f0, p1b1f0, colBase, q, 1); CP_COMMIT();
        CP_WAIT1();
        sum += computeP1<0,0>(BUF_P(0), acc, z2a0, z2b0, z2j, colBase, q, c0, c1);
        issueP1(BUF_A(0), gt4, p1b0f1, p1b1f1, colBase, q, 0); CP_COMMIT();
        CP_WAIT1();
        sum += computeP1<0,1>(BUF_P(1), acc, z2a0, z2b0, z2j, colBase, q, c0, c1);
        issueP1(BUF_A(1), gt4, p1b0f1, p1b1f1, colBase, q, 1); CP_COMMIT();
        CP_WAIT1();
        sum += computeP1<1,0>(BUF_P(0), acc, z2a1, z2b1, z2j, colBase, q, c0, c1);
        issueP2(BUF_A(0), gt2, p2f0, colBase, q, 0); CP_COMMIT();
        CP_WAIT1();
        sum += computeP1<1,1>(BUF_P(1), acc, z2a1, z2b1, z2j, colBase, q, c0, c1);
        issueP2(BUF_A(1), gt2, p2f0, colBase, q, 1); CP_COMMIT();
        CP_WAIT1();
        sum += computeP2<0,0>(BUF_P(0), acc, z2a0, z2b0, z2j, colBase, q, c0, c1);
        issueP2(BUF_A(0), gt2, p2f1, colBase, q, 0); CP_COMMIT();
        CP_WAIT1();
        sum += computeP2<0,1>(BUF_P(1), acc, z2a0, z2b0, z2j, colBase, q, c0, c1);
        issueP2(BUF_A(1), gt2, p2f1, colBase, q, 1); CP_COMMIT();
        CP_WAIT1();
        sum += computeP2<1,0>(BUF_P(0), acc, z2a1, z2b1, z2j, colBase, q, c0, c1);
        CP_WAIT0();
        sum += computeP2<1,1>(BUF_P(1), acc, z2a1, z2b1, z2j, colBase, q, c0, c1);
    } else {
        issueP1(BUF_A(0), gt4, p1b0f0, p1b1f0, colBase, q, 0); CP_COMMIT();
        issueP1(BUF_A(1), gt4, p1b0f0, p1b1f0, colBase, q, 1); CP_COMMIT();
        CP_WAIT1();
        sum += computeP1<0,0>(BUF_P(0), acc, z2a0, z2b0, z2j, colBase, q, c0, c1);
        issueP1(BUF_A(0), gt4, p1b0f1, p1b1f1, colBase, q, 0); CP_COMMIT();
        CP_WAIT1();
        sum += computeP1<0,1>(BUF_P(1), acc, z2a0, z2b0, z2j, colBase, q, c0, c1);
        issueP1(BUF_A(1), gt4, p1b0f1, p1b1f1, colBase, q, 1); CP_COMMIT();
        CP_WAIT1();
        sum += computeP1<1,0>(BUF_P(0), acc, z2a1, z2b1, z2j, colBase, q, c0, c1);
        CP_WAIT0();
        sum += computeP1<1,1>(BUF_P(1), acc, z2a1, z2b1, z2j, colBase, q, c0, c1);
    }

    // ---- block reduce -> per-CTA partial ----
    #pragma unroll
    for (int o = 16; o; o >>= 1) sum += __shfl_xor_sync(0xffffffffu, sum, o);
    __shared__ float wsum[8];
    __shared__ int isLast;
    if (lane == 0) wsum[warp] = sum;
    __syncthreads();
    if (tid == 0) {
        float t = 0.f;
        #pragma unroll
        for (int w = 0; w < 8; w++) t += wsum[w];
        g_part[b * NPAIR + blockIdx.x] = (double)t;
        __threadfence();
        int old = atomicAdd(&g_ticket, 1);
        isLast = (old == NPART - 1);
    }
    __syncthreads();

    // ---- last CTA: deterministic final reduce (fixed index order) ----
    if (isLast) {
        double s = 0.0;
        for (int i = tid; i < NPART; i += 256) s += g_part[i];
        __shared__ double sh[256];
        sh[tid] = s;
        __syncthreads();
        for (int o = 128; o; o >>= 1) {
            if (tid < o) sh[tid] += sh[tid + o];
            __syncthreads();
        }
        if (tid == 0) {
            out[0] = (float)(sh[0] / ((double)Bn * (double)Tn * (double)Tn));
            g_ticket = 0;   // reset for next graph replay
        }
    }
}

// ============================================================
extern "C" void kernel_launch(void* const* d_in, const int* in_sizes, int n_in,
                              void* d_out, int out_size) {
    const float *z = nullptr, *gt = nullptr, *sg = nullptr;
    for (int i = 0; i < n_in; i++) {
        if (in_sizes[i] == Bn * Tn * Dn)      z  = (const float*)d_in[i];
        else if (in_sizes[i] == 2)            sg = (const float*)d_in[i];
        else                                  gt = (const float*)d_in[i];
    }

    cudaFuncSetAttribute(main_kernel,
                         cudaFuncAttributeMaxDynamicSharedMemorySize, SMEM_BYTES);

    prep_kernel<<<Bn * Tn / 32, 256>>>(z);
    dim3 grid(NPAIR, Bn);
    main_kernel<<<grid, 256, SMEM_BYTES>>>(gt, sg, (float*)d_out);
}